// round 1
// baseline (speedup 1.0000x reference)
#include <cuda_runtime.h>

// Trilinear multi-resolution feature sampling.
// Levels used: 1 (64^3 x 32), 2 (32^3 x 64), 3 (16^3 x 128).
// Output per point: [lev1 32ch | lev2 64ch | lev3 128ch | mesh 3ch] = 227 floats.
//
// Thread mapping: 64 threads per point. slot = tid & 63.
//   slot 0..7   -> level 1, channels 4*slot .. (within level: 4*slot)
//   slot 8..23  -> level 2
//   slot 24..55 -> level 3
//   slot 56..58 -> mesh feature passthrough
// Concat offsets align so global out channel = 4*slot for slots 0..55.

static __device__ __forceinline__ float4 lerp4(float4 a, float4 b, float wa, float wb) {
    float4 r;
    r.x = fmaf(a.x, wa, b.x * wb);
    r.y = fmaf(a.y, wa, b.y * wb);
    r.z = fmaf(a.z, wa, b.z * wb);
    r.w = fmaf(a.w, wa, b.w * wb);
    return r;
}

__global__ void __launch_bounds__(256) trilerp_kernel(
    const float* __restrict__ f1, const float* __restrict__ f2, const float* __restrict__ f3,
    const float* __restrict__ coords, const float* __restrict__ meshf,
    float* __restrict__ out, int BN, unsigned N)
{
    int gid = blockIdx.x * 256 + threadIdx.x;
    int point = gid >> 6;
    int slot = gid & 63;
    if (point >= BN) return;

    if (slot >= 56) {
        int k = slot - 56;
        if (k < 3) out[(size_t)point * 227 + 224 + k] = meshf[point * 3 + k];
        return;
    }

    // Per-point coordinates (broadcast loads, L1/L2 hits across the 64-thread group)
    float cx = coords[point * 3 + 0];
    float cy = coords[point * 3 + 1];
    float cz = coords[point * 3 + 2];

    // Level parameters via selects (no heavy divergence; single shared trilerp path)
    int lev = (slot < 8) ? 1 : ((slot < 24) ? 2 : 3);
    const float* feat = (lev == 1) ? f1 : ((lev == 2) ? f2 : f3);
    int cstart = (lev == 1) ? 0 : ((lev == 2) ? 8 : 24);
    int R = 128 >> lev;          // 64 / 32 / 16
    int C = 16 << lev;           // 32 / 64 / 128
    int c = (slot - cstart) * 4; // channel base within this level

    unsigned b = (unsigned)point / N;

    float scale = (float)R;      // 0.5^lev * 128 == R
    float hi = scale - 1.01f;

    float ix = fminf(fmaxf(cx * scale, 0.01f), hi);
    float iy = fminf(fmaxf(cy * scale, 0.01f), hi);
    float iz = fminf(fmaxf(cz * scale, 0.01f), hi);

    float fx1 = floorf(ix), fx2 = ceilf(ix);
    float fy1 = floorf(iy), fy2 = ceilf(iy);
    float fz1 = floorf(iz), fz2 = ceilf(iz);

    float wx = ix - fx1, wx2 = fx2 - ix;
    float wy = iy - fy1, wy2 = fy2 - iy;
    float wz = iz - fz1, wz2 = fz2 - iz;

    int x1 = (int)fx1, x2 = (int)fx2;
    int y1 = (int)fy1, y2 = (int)fy2;
    int z1 = (int)fz1, z2 = (int)fz2;

    // Strides in float4 units (C divisible by 4, c divisible by 4 -> aligned)
    int zs4 = C >> 2;
    int ys4 = R * zs4;
    int xs4 = R * ys4;
    int b4  = (int)b * R * xs4 + (c >> 2);

    const float4* __restrict__ fp = (const float4*)feat;

    float4 v111 = fp[b4 + x1 * xs4 + y1 * ys4 + z1 * zs4];
    float4 v211 = fp[b4 + x2 * xs4 + y1 * ys4 + z1 * zs4];
    float4 v121 = fp[b4 + x1 * xs4 + y2 * ys4 + z1 * zs4];
    float4 v221 = fp[b4 + x2 * xs4 + y2 * ys4 + z1 * zs4];
    float4 v112 = fp[b4 + x1 * xs4 + y1 * ys4 + z2 * zs4];
    float4 v212 = fp[b4 + x2 * xs4 + y1 * ys4 + z2 * zs4];
    float4 v122 = fp[b4 + x1 * xs4 + y2 * ys4 + z2 * zs4];
    float4 v222 = fp[b4 + x2 * xs4 + y2 * ys4 + z2 * zs4];

    // z = z1 plane
    float4 la  = lerp4(v211, v111, wx, wx2);
    float4 lb  = lerp4(v221, v121, wx, wx2);
    float4 ly1 = lerp4(lb, la, wy, wy2);
    // z = z2 plane
    float4 lc  = lerp4(v212, v112, wx, wx2);
    float4 ld  = lerp4(v222, v122, wx, wx2);
    float4 ly2 = lerp4(ld, lc, wy, wy2);

    float4 r = lerp4(ly2, ly1, wz, wz2);

    // 227 stride breaks 16B alignment -> scalar stores (stores are ~11% of traffic)
    size_t o = (size_t)point * 227 + 4 * slot;
    out[o + 0] = r.x;
    out[o + 1] = r.y;
    out[o + 2] = r.z;
    out[o + 3] = r.w;
}

extern "C" void kernel_launch(void* const* d_in, const int* in_sizes, int n_in,
                              void* d_out, int out_size)
{
    // metadata order: features0, features1, features2, features3, features4,
    //                 mesh_coords, mesh_features
    const float* f1     = (const float*)d_in[1];
    const float* f2     = (const float*)d_in[2];
    const float* f3     = (const float*)d_in[3];
    const float* coords = (const float*)d_in[5];
    const float* meshf  = (const float*)d_in[6];
    float* out = (float*)d_out;

    int B  = in_sizes[1] / (64 * 64 * 64 * 32);
    int BN = in_sizes[5] / 3;           // total points across batch
    unsigned N = (unsigned)(BN / B);

    long long threads = (long long)BN * 64;
    int blocks = (int)((threads + 255) / 256);
    trilerp_kernel<<<blocks, 256>>>(f1, f2, f3, coords, meshf, out, BN, N);
}